// round 10
// baseline (speedup 1.0000x reference)
#include <cuda_runtime.h>
#include <cstdint>
#include <cstddef>

namespace {

constexpr int kB   = 4096;
constexpr int kN   = 64;
constexpr int kOBS = 192;
constexpr int kACT = 64;
constexpr int kIN  = 256;
constexpr int kD   = 128;
constexpr int kFO  = 64;

constexpr int kThreads = 512;  // 16 warps

// strides ≡ 8 (mod 32): conflict-free float2 fragment loads (R8/R9-proven)
constexpr int SA_LD = 264;
constexpr int E_LD  = 136;
constexpr int S_LD  = 72;
constexpr int WG_LD = 40;

// SMEM pool (floats) — R9 plan
constexpr int OFF_SA = 0;
constexpr int OFF_T  = 0;
constexpr int OFF_SC = 8704;
constexpr int OFF_H  = 0;
constexpr int OFF_E  = 16896;
constexpr int OFF_EQ = 25600;
constexpr int OFF_VT = 34304;
constexpr int OFF_W0 = 43520;
constexpr int OFF_W1 = 48640;
constexpr int SMEM_FLOATS = 53760;
constexpr int SMEM_BYTES  = SMEM_FLOATS * 4;  // 215040

// Pre-packed weight chunks (tf32-rounded, pk/rperm applied, SMEM-image layout)
constexpr int CH  = 128 * WG_LD;  // 5120 floats per 128-row chunk
constexpr int CHS = 64 * WG_LD;   // 2560 floats per 64-row chunk
constexpr int OPK_E  = 0;              // 8 chunks
constexpr int OPK_EQ = 8 * CH;         // 8 chunks
constexpr int OPK_T  = 16 * CH;        // 4 chunks (Mt)
constexpr int OPK_V  = 20 * CH;        // 4 chunks
constexpr int OPK_F1 = 24 * CH;        // 8 chunks of CHS
constexpr int OPK_F2 = 24 * CH + 8 * CHS;  // 2 chunks of CHS
constexpr int PK_TOTAL = 24 * CH + 10 * CHS;  // 148480 floats
__device__ float gWP[PK_TOTAL];

__device__ __forceinline__ float f2tf(float x) {
  uint32_t u;
  asm("cvt.rna.tf32.f32 %0, %1;" : "=r"(u) : "f"(x));
  return __uint_as_float(u);
}

// packing within 8-groups: logical k -> packed pos, (k,k+4) adjacent.
__device__ __forceinline__ int pk(int k) {
  return (k & ~7) + 2 * (k & 3) + ((k >> 2) & 1);
}

__device__ __forceinline__ void mma8(float (&d)[4], const uint32_t (&a)[4],
                                     const uint32_t (&b)[2]) {
  asm volatile(
      "mma.sync.aligned.m16n8k8.row.col.f32.tf32.tf32.f32 "
      "{%0,%1,%2,%3}, {%4,%5,%6,%7}, {%8,%9}, {%0,%1,%2,%3};\n"
      : "+f"(d[0]), "+f"(d[1]), "+f"(d[2]), "+f"(d[3])
      : "r"(a[0]), "r"(a[1]), "r"(a[2]), "r"(a[3]), "r"(b[0]), "r"(b[1]));
}

// R9-proven float2 fragment loads; A/B pk-packed along k.
template <int NT, int KC>
__device__ __forceinline__ void mma_block(const float* __restrict__ As, int lda,
                                          const float* __restrict__ Bs, int ldb,
                                          float (&d)[2][NT][4],
                                          int lane, int wm, int wn) {
  const float* Aw = As + (wm * 32) * lda;
  const float* Bw = Bs + (wn * NT * 8) * ldb;
  const int gr = lane >> 2, gc = lane & 3;
#pragma unroll
  for (int k0 = 0; k0 < KC; k0 += 8) {
    uint32_t a[2][4];
#pragma unroll
    for (int mt = 0; mt < 2; mt++) {
      float2 v0 = *(const float2*)(Aw + (mt * 16 + gr) * lda + k0 + 2 * gc);
      float2 v1 = *(const float2*)(Aw + (mt * 16 + 8 + gr) * lda + k0 + 2 * gc);
      a[mt][0] = __float_as_uint(v0.x);
      a[mt][1] = __float_as_uint(v1.x);
      a[mt][2] = __float_as_uint(v0.y);
      a[mt][3] = __float_as_uint(v1.y);
    }
#pragma unroll
    for (int nt = 0; nt < NT; nt++) {
      float2 bv = *(const float2*)(Bw + (nt * 8 + gr) * ldb + k0 + 2 * gc);
      uint32_t bf[2] = {__float_as_uint(bv.x), __float_as_uint(bv.y)};
      mma8(d[0][nt], a[0], bf);
      mma8(d[1][nt], a[1], bf);
    }
  }
}

// Pair-wise epilogue (R9-proven): f(row, cphys, lo, hi); with rperm'd weights
// cphys is the packed destination index (identity).
template <int NT, class F>
__device__ __forceinline__ void for_each_pair(float (&d)[2][NT][4], int lane,
                                              int wm, int wn, F f) {
  const int gr = lane >> 2;
  const int gc2 = (lane & 3) * 2;
#pragma unroll
  for (int mt = 0; mt < 2; mt++)
#pragma unroll
    for (int nt = 0; nt < NT; nt++) {
      int col = wn * NT * 8 + nt * 8 + gc2;
      int row = wm * 32 + mt * 16 + gr;
      f(row, col, d[mt][nt][0], d[mt][nt][1]);
      f(row + 8, col, d[mt][nt][2], d[mt][nt][3]);
    }
}

template <int NT>
__device__ __forceinline__ void zero_acc(float (&d)[2][NT][4]) {
#pragma unroll
  for (int mt = 0; mt < 2; mt++)
#pragma unroll
    for (int nt = 0; nt < NT; nt++)
#pragma unroll
      for (int i = 0; i < 4; i++) d[mt][nt][i] = 0.f;
}

// ---- cp.async staging of pre-packed chunks (contiguous copy)
__device__ __forceinline__ void cp16(uint32_t saddr, const float* __restrict__ g) {
  asm volatile("cp.async.ca.shared.global [%0], [%1], 16;\n"
               :: "r"(saddr), "l"(g) : "memory");
}
template <int FCNT>
__device__ __forceinline__ void cpa_chunk(float* dst, const float* __restrict__ src,
                                          int tid) {
  uint32_t s0 = (uint32_t)__cvta_generic_to_shared(dst);
#pragma unroll
  for (int i = tid; i < FCNT / 4; i += kThreads)
    cp16(s0 + (uint32_t)i * 16u, src + i * 4);
  asm volatile("cp.async.commit_group;\n" ::: "memory");
}
__device__ __forceinline__ void cpa_wait() {
  asm volatile("cp.async.wait_group 0;\n" ::: "memory");
}

// Double-buffered staged matmul over NCH pre-packed chunks; 1 sync/chunk.
template <int NT, int NCH, int FCNT>
__device__ __forceinline__ void staged_mm(const float* __restrict__ A, int lda,
                                          const float* __restrict__ wsrc,
                                          float (&d)[2][NT][4],
                                          float* w0, float* w1, int tid,
                                          int lane, int wm, int wn) {
  cpa_chunk<FCNT>(w0, wsrc, tid);
  cpa_wait();
  __syncthreads();
#pragma unroll
  for (int c = 0; c < NCH; c++) {
    float* cur = (c & 1) ? w1 : w0;
    float* nxt = (c & 1) ? w0 : w1;
    const bool more = (c + 1 < NCH);
    if (more) cpa_chunk<FCNT>(nxt, wsrc + (c + 1) * FCNT, tid);
    mma_block<NT, 32>(A + c * 32, lda, cur, WG_LD, d, lane, wm, wn);
    if (more) cpa_wait();
    __syncthreads();
  }
}

// ---- prologue A: pack a weight matrix into SMEM-image chunks in gWP.
// dst[c*On*WG_LD + (rperm? pk(o):o)*WG_LD + pk(k)] = f2tf(W[o*Kfull + c*32+k])
__global__ void pack_w(const float* __restrict__ W, int On, int Kfull,
                       int nch, int dst_off, int rperm) {
  int idx = blockIdx.x * 256 + threadIdx.x;
  int total = nch * On * 32;
  if (idx >= total) return;
  int c = idx / (On * 32);
  int rem = idx - c * (On * 32);
  int o = rem >> 5, k = rem & 31;
  int op = rperm ? pk(o) : o;
  gWP[dst_off + c * On * WG_LD + op * WG_LD + pk(k)] =
      f2tf(W[o * Kfull + c * 32 + k]);
}

// ---- prologue B: Mt[j][i] = sum_d Wq[d][i]*Wk[d][j], written packed.
__global__ void precompute_mt(const float* __restrict__ Wq,
                              const float* __restrict__ Wk) {
  __shared__ float wkj[kD];
  const int j = blockIdx.x;
  const int i = threadIdx.x;
  wkj[i] = Wk[i * kD + j];
  __syncthreads();
  float s = 0.f;
#pragma unroll 8
  for (int dd = 0; dd < kD; dd++) s += Wq[dd * kD + i] * wkj[dd];
  int c = i >> 5, k = i & 31;
  gWP[OPK_T + c * CH + pk(j) * WG_LD + pk(k)] = f2tf(s);
}

__global__ __launch_bounds__(kThreads, 1)
void critic_kernel(const float* __restrict__ states,
                   const float* __restrict__ actions,
                   const float* __restrict__ b_embed,
                   const float* __restrict__ b_embed_q,
                   float* __restrict__ outV,
                   float* __restrict__ outW) {
  extern __shared__ float smem[];
  const int b = blockIdx.x;
  const int tid = threadIdx.x;
  const int lane = tid & 31;
  const int warp = tid >> 5;
  const int wm = warp >> 3, wn = warp & 7;  // 16-warp grid everywhere
  const int gr = lane >> 2;
  const int pkgr = 2 * (gr & 3) + ((gr >> 2) & 1);  // pk8(gr), hoisted

  float* SA = smem + OFF_SA;
  float* T  = smem + OFF_T;
  float* SC = smem + OFF_SC;
  float* H  = smem + OFF_H;
  float* E  = smem + OFF_E;
  float* EQ = smem + OFF_EQ;
  float* VT = smem + OFF_VT;
  float* W0 = smem + OFF_W0;
  float* W1 = smem + OFF_W1;

  // ---- load sa, pk-packed (first staged sync covers visibility)
  {
    const float* st = states + (size_t)b * kN * kOBS;
    const float* ac = actions + (size_t)b * kN * kACT;
#pragma unroll 4
    for (int j = 0; j < 32; j++) {
      int i = tid + j * kThreads;
      int t = i >> 8, c = i & 255;
      float v = (c < kOBS) ? st[t * kOBS + c] : ac[t * kACT + (c - kOBS)];
      SA[t * SA_LD + pk(c)] = f2tf(v);
    }
  }

  float d2[2][2][4];
  float d1[2][1][4];

  // ---- e = lrelu(sa @ W_embed^T + b)  [64,128]  (16 warps, 32x16 tiles)
  zero_acc(d2);
  staged_mm<2, 8, CH>(SA, SA_LD, gWP + OPK_E, d2, W0, W1, tid, lane, wm, wn);
  for_each_pair<2>(d2, lane, wm, wn, [&](int r, int c, float lo, float hi) {
    int lg = (c & ~7) + ((c & 7) >> 1);  // logical col of lo; hi = lg+4
    lo += __ldg(b_embed + lg);
    hi += __ldg(b_embed + lg + 4);
    lo = lo > 0.f ? lo : 0.01f * lo;
    hi = hi > 0.f ? hi : 0.01f * hi;
    *(float2*)(E + r * E_LD + c) = make_float2(f2tf(lo), f2tf(hi));
  });

  // ---- eq = lrelu(sa @ W_embed_q^T + b_q)
  zero_acc(d2);
  staged_mm<2, 8, CH>(SA, SA_LD, gWP + OPK_EQ, d2, W0, W1, tid, lane, wm, wn);
  for_each_pair<2>(d2, lane, wm, wn, [&](int r, int c, float lo, float hi) {
    int lg = (c & ~7) + ((c & 7) >> 1);
    lo += __ldg(b_embed_q + lg);
    hi += __ldg(b_embed_q + lg + 4);
    lo = lo > 0.f ? lo : 0.01f * lo;
    hi = hi > 0.f ? hi : 0.01f * hi;
    *(float2*)(EQ + r * E_LD + c) = make_float2(f2tf(lo), f2tf(hi));
  });
  __syncthreads();  // SA fully dead; T may alias

  // ---- t = e @ Mt^T  (identity-packed epilogue)
  zero_acc(d2);
  staged_mm<2, 4, CH>(E, E_LD, gWP + OPK_T, d2, W0, W1, tid, lane, wm, wn);
  for_each_pair<2>(d2, lane, wm, wn, [&](int r, int c, float lo, float hi) {
    *(float2*)(T + r * E_LD + c) = make_float2(f2tf(lo), f2tf(hi));
  });

  // ---- v = e @ W_v^T, transposed into VT[dphys][token-packed]
  zero_acc(d2);
  staged_mm<2, 4, CH>(E, E_LD, gWP + OPK_V, d2, W0, W1, tid, lane, wm, wn);
  for_each_pair<2>(d2, lane, wm, wn, [&](int r, int c, float lo, float hi) {
    int rp = (r & ~7) + pkgr;  // packed token index
    VT[c * S_LD + rp] = f2tf(lo);
    VT[(c + 1) * S_LD + rp] = f2tf(hi);
  });
  __syncthreads();  // T, VT visible

  // ---- scores = t @ e^T / sqrt(D) -> SC fp32 (16 warps)
  zero_acc(d1);
  mma_block<1, 128>(T, E_LD, E, E_LD, d1, lane, wm, wn);
  for_each_pair<1>(d1, lane, wm, wn, [&](int r, int c, float lo, float hi) {
    *(float2*)(SC + r * S_LD + c) =
        make_float2(lo * 0.08838834764831845f, hi * 0.08838834764831845f);
  });
  __syncthreads();

  // ---- row softmax: gmem fp32 logical + packed tf32 back into SC
  {
    const int r = tid >> 3;
    const int c0 = (tid & 7) * 8;
    float* wrow = SC + r * S_LD + c0;
    float s[8];
#pragma unroll
    for (int j = 0; j < 8; j++) s[j] = wrow[j];
    float mx = -3.0e38f;
#pragma unroll
    for (int j = 0; j < 8; j++) mx = fmaxf(mx, s[j]);
    mx = fmaxf(mx, __shfl_xor_sync(0xffffffffu, mx, 1));
    mx = fmaxf(mx, __shfl_xor_sync(0xffffffffu, mx, 2));
    mx = fmaxf(mx, __shfl_xor_sync(0xffffffffu, mx, 4));
    float sum = 0.f;
#pragma unroll
    for (int j = 0; j < 8; j++) {
      s[j] = __expf(s[j] - mx);
      sum += s[j];
    }
    sum += __shfl_xor_sync(0xffffffffu, sum, 1);
    sum += __shfl_xor_sync(0xffffffffu, sum, 2);
    sum += __shfl_xor_sync(0xffffffffu, sum, 4);
    float inv = 1.f / sum;
    float* og = outW + ((size_t)b * kN + r) * kN + c0;
#pragma unroll
    for (int j = 0; j < 8; j++) {
      float wv = s[j] * inv;
      og[j] = wv;
      wrow[2 * (j & 3) + (j >> 2)] = f2tf(wv);
    }
  }
  __syncthreads();

  // ---- x = weight @ v -> E (identity-packed: VT rows are physical)
  zero_acc(d2);
  mma_block<2, 64>(SC, S_LD, VT, S_LD, d2, lane, wm, wn);
  for_each_pair<2>(d2, lane, wm, wn, [&](int r, int c, float lo, float hi) {
    *(float2*)(E + r * E_LD + c) = make_float2(f2tf(lo), f2tf(hi));
  });
  __syncthreads();

  // ---- h = lrelu([eq, x] @ W_f1^T)  (accumulate halves)
  zero_acc(d1);
  staged_mm<1, 4, CHS>(EQ, E_LD, gWP + OPK_F1, d1, W0, W1, tid, lane, wm, wn);
  staged_mm<1, 4, CHS>(E, E_LD, gWP + OPK_F1 + 4 * CHS, d1, W0, W1, tid, lane,
                       wm, wn);
  for_each_pair<1>(d1, lane, wm, wn, [&](int r, int c, float lo, float hi) {
    lo = lo > 0.f ? lo : 0.01f * lo;
    hi = hi > 0.f ? hi : 0.01f * hi;
    *(float2*)(H + r * S_LD + c) = make_float2(f2tf(lo), f2tf(hi));
  });

  // ---- Value = h @ W_f2^T -> gmem (f2 staged without rperm -> logical cols)
  zero_acc(d1);
  staged_mm<1, 2, CHS>(H, S_LD, gWP + OPK_F2, d1, W0, W1, tid, lane, wm, wn);
  for_each_pair<1>(d1, lane, wm, wn, [&](int r, int c, float lo, float hi) {
    *(float2*)(outV + ((size_t)b * kN + r) * kFO + c) = make_float2(lo, hi);
  });
}

}  // namespace

extern "C" void kernel_launch(void* const* d_in, const int* in_sizes, int n_in,
                              void* d_out, int out_size) {
  (void)in_sizes; (void)n_in; (void)out_size;
  const float* states    = (const float*)d_in[0];
  const float* actions   = (const float*)d_in[1];
  const float* W_embed   = (const float*)d_in[2];
  const float* b_embed   = (const float*)d_in[3];
  const float* W_k       = (const float*)d_in[4];
  const float* W_q       = (const float*)d_in[5];
  const float* W_v       = (const float*)d_in[6];
  const float* W_embed_q = (const float*)d_in[7];
  const float* b_embed_q = (const float*)d_in[8];
  const float* W_f1      = (const float*)d_in[9];
  const float* W_f2      = (const float*)d_in[10];

  float* outV = (float*)d_out;                 // Value [B,N,64]
  float* outW = outV + (size_t)kB * kN * kFO;  // weight [B,N,N]

  precompute_mt<<<kD, kD>>>(W_q, W_k);
  pack_w<<<(8 * 128 * 32 + 255) / 256, 256>>>(W_embed, 128, kIN, 8, OPK_E, 1);
  pack_w<<<(8 * 128 * 32 + 255) / 256, 256>>>(W_embed_q, 128, kIN, 8, OPK_EQ, 1);
  pack_w<<<(4 * 128 * 32 + 255) / 256, 256>>>(W_v, 128, kD, 4, OPK_V, 1);
  pack_w<<<(8 * 64 * 32 + 255) / 256, 256>>>(W_f1, 64, 2 * kD, 8, OPK_F1, 1);
  pack_w<<<(2 * 64 * 32 + 255) / 256, 256>>>(W_f2, 64, kN, 2, OPK_F2, 0);

  cudaFuncSetAttribute(critic_kernel,
                       cudaFuncAttributeMaxDynamicSharedMemorySize, SMEM_BYTES);
  critic_kernel<<<kB, kThreads, SMEM_BYTES>>>(states, actions, b_embed,
                                              b_embed_q, outV, outW);
}

// round 11
// speedup vs baseline: 1.0635x; 1.0635x over previous
#include <cuda_runtime.h>
#include <cstdint>
#include <cstddef>

namespace {

constexpr int kB   = 4096;
constexpr int kN   = 64;
constexpr int kOBS = 192;
constexpr int kACT = 64;
constexpr int kIN  = 256;
constexpr int kD   = 128;
constexpr int kFO  = 64;

constexpr int kThreads = 512;  // 16 warps

// strides ≡ 8 (mod 32): conflict-free float2 fragment loads
constexpr int SA_LD = 264;
constexpr int E_LD  = 136;
constexpr int S_LD  = 72;
constexpr int WG_LD = 40;

// SMEM pool (floats)
constexpr int OFF_W  = 0;       // W stage buffer [256x40] = 10240
constexpr int OFF_SA = 10240;   // sa [64x264]=16896; later T(+0,8704) + SC(+8704,4608); H(+0)
constexpr int OFF_T  = 10240;
constexpr int OFF_SC = 18944;
constexpr int OFF_H  = 10240;
constexpr int OFF_E  = 27136;   // e [64x136]; later x
constexpr int OFF_EQ = 35840;   // eq [64x136]
constexpr int OFF_VT = 44544;   // v^T [128x72] = 9216
constexpr int SMEM_FLOATS = 53760;
constexpr int SMEM_BYTES  = SMEM_FLOATS * 4;  // 215040

// Pre-packed weights (tf32-rounded, pk k-packing, pk row-perm, SMEM image)
constexpr int CHEE = 256 * WG_LD;  // 10240 per merged 256-row chunk
constexpr int CHS  = 64 * WG_LD;   // 2560 per 64-row chunk
constexpr int OPK_EE = 0;                   // 8 chunks [We;Weq]
constexpr int OPK_TV = 8 * CHEE;            // 4 chunks [Mt;Wv]
constexpr int OPK_F1 = 8 * CHEE + 4 * CHEE; // 8 chunks (64-row)
constexpr int OPK_F2 = OPK_F1 + 8 * CHS;    // 2 chunks
constexpr int PK_TOTAL = OPK_F2 + 2 * CHS;  // 148480
__device__ float gWP[PK_TOTAL];

__device__ __forceinline__ float f2tf(float x) {
  uint32_t u;
  asm("cvt.rna.tf32.f32 %0, %1;" : "=r"(u) : "f"(x));
  return __uint_as_float(u);
}

// packing within 8-groups: (k, k+4) adjacent
__device__ __forceinline__ int pk(int k) {
  return (k & ~7) + 2 * (k & 3) + ((k >> 2) & 1);
}

__device__ __forceinline__ void mma8(float (&d)[4], const uint32_t (&a)[4],
                                     const uint32_t (&b)[2]) {
  asm volatile(
      "mma.sync.aligned.m16n8k8.row.col.f32.tf32.tf32.f32 "
      "{%0,%1,%2,%3}, {%4,%5,%6,%7}, {%8,%9}, {%0,%1,%2,%3};\n"
      : "+f"(d[0]), "+f"(d[1]), "+f"(d[2]), "+f"(d[3])
      : "r"(a[0]), "r"(a[1]), "r"(a[2]), "r"(a[3]), "r"(b[0]), "r"(b[1]));
}

// R9/R10-proven float2 fragment loads; pk-packed along k.
template <int NT, int KC>
__device__ __forceinline__ void mma_block(const float* __restrict__ As, int lda,
                                          const float* __restrict__ Bs, int ldb,
                                          float (&d)[2][NT][4],
                                          int lane, int wm, int wn) {
  const float* Aw = As + (wm * 32) * lda;
  const float* Bw = Bs + (wn * NT * 8) * ldb;
  const int gr = lane >> 2, gc = lane & 3;
#pragma unroll
  for (int k0 = 0; k0 < KC; k0 += 8) {
    uint32_t a[2][4];
#pragma unroll
    for (int mt = 0; mt < 2; mt++) {
      float2 v0 = *(const float2*)(Aw + (mt * 16 + gr) * lda + k0 + 2 * gc);
      float2 v1 = *(const float2*)(Aw + (mt * 16 + 8 + gr) * lda + k0 + 2 * gc);
      a[mt][0] = __float_as_uint(v0.x);
      a[mt][1] = __float_as_uint(v1.x);
      a[mt][2] = __float_as_uint(v0.y);
      a[mt][3] = __float_as_uint(v1.y);
    }
#pragma unroll
    for (int nt = 0; nt < NT; nt++) {
      float2 bv = *(const float2*)(Bw + (nt * 8 + gr) * ldb + k0 + 2 * gc);
      uint32_t bf[2] = {__float_as_uint(bv.x), __float_as_uint(bv.y)};
      mma8(d[0][nt], a[0], bf);
      mma8(d[1][nt], a[1], bf);
    }
  }
}

// Pair-wise epilogue (R9/R10-proven): cphys is the packed dest index.
template <int NT, class F>
__device__ __forceinline__ void for_each_pair(float (&d)[2][NT][4], int lane,
                                              int wm, int wn, F f) {
  const int gr = lane >> 2;
  const int gc2 = (lane & 3) * 2;
#pragma unroll
  for (int mt = 0; mt < 2; mt++)
#pragma unroll
    for (int nt = 0; nt < NT; nt++) {
      int col = wn * NT * 8 + nt * 8 + gc2;
      int row = wm * 32 + mt * 16 + gr;
      f(row, col, d[mt][nt][0], d[mt][nt][1]);
      f(row + 8, col, d[mt][nt][2], d[mt][nt][3]);
    }
}

template <int NT>
__device__ __forceinline__ void zero_acc(float (&d)[2][NT][4]) {
#pragma unroll
  for (int mt = 0; mt < 2; mt++)
#pragma unroll
    for (int nt = 0; nt < NT; nt++)
#pragma unroll
      for (int i = 0; i < 4; i++) d[mt][nt][i] = 0.f;
}

// ---- cp.async staging of pre-packed chunks (contiguous copies)
__device__ __forceinline__ void cp16(uint32_t saddr, const float* __restrict__ g) {
  asm volatile("cp.async.ca.shared.global [%0], [%1], 16;\n"
               :: "r"(saddr), "l"(g) : "memory");
}
template <int FCNT>
__device__ __forceinline__ void cpa_chunk(float* dst, const float* __restrict__ src,
                                          int tid) {
  uint32_t s0 = (uint32_t)__cvta_generic_to_shared(dst);
#pragma unroll
  for (int i = tid; i < FCNT / 4; i += kThreads)
    cp16(s0 + (uint32_t)i * 16u, src + i * 4);
  asm volatile("cp.async.commit_group;\n" ::: "memory");
}
__device__ __forceinline__ void cpa_wait() {
  asm volatile("cp.async.wait_group 0;\n" ::: "memory");
}

// Merged big stage: single buffer, 2 syncs/chunk (R6-proven barrier pattern),
// 16 warps at MT2/NT4 over 256 output cols.
template <int NCH>
__device__ __forceinline__ void staged_big(const float* __restrict__ A, int lda,
                                           const float* __restrict__ wsrc,
                                           float (&d)[2][4][4], float* W,
                                           int tid, int lane, int wm, int wn) {
#pragma unroll
  for (int c = 0; c < NCH; c++) {
    __syncthreads();  // previous consumers of W done
    cpa_chunk<CHEE>(W, wsrc + c * CHEE, tid);
    cpa_wait();
    __syncthreads();  // chunk visible
    mma_block<4, 32>(A + c * 32, lda, W, WG_LD, d, lane, wm, wn);
  }
}

// Small stage: double-buffered halves of W, 1 sync/chunk (R10-proven).
template <int NCH>
__device__ __forceinline__ void staged_small(const float* __restrict__ A, int lda,
                                             const float* __restrict__ wsrc,
                                             float (&d)[2][1][4], float* W,
                                             int tid, int lane, int wm, int wn) {
  float* w0 = W;
  float* w1 = W + 5120;
  cpa_chunk<CHS>(w0, wsrc, tid);
  cpa_wait();
  __syncthreads();
#pragma unroll
  for (int c = 0; c < NCH; c++) {
    float* cur = (c & 1) ? w1 : w0;
    float* nxt = (c & 1) ? w0 : w1;
    const bool more = (c + 1 < NCH);
    if (more) cpa_chunk<CHS>(nxt, wsrc + (c + 1) * CHS, tid);
    mma_block<1, 32>(A + c * 32, lda, cur, WG_LD, d, lane, wm, wn);
    if (more) cpa_wait();
    __syncthreads();
  }
}

// ---- prologue A: pack W into merged SMEM-image chunks
__global__ void pack_w(const float* __restrict__ W, int On, int Kfull,
                       int nch, int dst_off, int chunk_rows, int row_base,
                       int rperm) {
  int idx = blockIdx.x * 256 + threadIdx.x;
  int total = nch * On * 32;
  if (idx >= total) return;
  int c = idx / (On * 32);
  int rem = idx - c * (On * 32);
  int o = rem >> 5, k = rem & 31;
  int op = row_base + (rperm ? pk(o) : o);
  gWP[dst_off + c * chunk_rows * WG_LD + op * WG_LD + pk(k)] =
      f2tf(W[o * Kfull + c * 32 + k]);
}

// ---- prologue B: Mt[j][i] = sum_d Wq[d][i]*Wk[d][j] -> rows 0-127 of TV chunks
__global__ void precompute_mt(const float* __restrict__ Wq,
                              const float* __restrict__ Wk) {
  __shared__ float wkj[kD];
  const int j = blockIdx.x;
  const int i = threadIdx.x;
  wkj[i] = Wk[i * kD + j];
  __syncthreads();
  float s = 0.f;
#pragma unroll 8
  for (int dd = 0; dd < kD; dd++) s += Wq[dd * kD + i] * wkj[dd];
  int c = i >> 5, k = i & 31;
  gWP[OPK_TV + c * CHEE + pk(j) * WG_LD + pk(k)] = f2tf(s);
}

__global__ __launch_bounds__(kThreads, 1)
void critic_kernel(const float* __restrict__ states,
                   const float* __restrict__ actions,
                   const float* __restrict__ b_embed,
                   const float* __restrict__ b_embed_q,
                   float* __restrict__ outV,
                   float* __restrict__ outW) {
  extern __shared__ float smem[];
  const int b = blockIdx.x;
  const int tid = threadIdx.x;
  const int lane = tid & 31;
  const int warp = tid >> 5;
  const int wm = warp >> 3, wn = warp & 7;  // 16-warp grid
  const int gr = lane >> 2;
  const int pkgr = 2 * (gr & 3) + ((gr >> 2) & 1);  // pk8(gr)

  float* W  = smem + OFF_W;
  float* SA = smem + OFF_SA;
  float* T  = smem + OFF_T;
  float* SC = smem + OFF_SC;
  float* H  = smem + OFF_H;
  float* E  = smem + OFF_E;
  float* EQ = smem + OFF_EQ;
  float* VT = smem + OFF_VT;

  // ---- load sa, pk-packed (first staged sync covers visibility)
  {
    const float* st = states + (size_t)b * kN * kOBS;
    const float* ac = actions + (size_t)b * kN * kACT;
#pragma unroll 4
    for (int j = 0; j < 32; j++) {
      int i = tid + j * kThreads;
      int t = i >> 8, c = i & 255;
      float v = (c < kOBS) ? st[t * kOBS + c] : ac[t * kACT + (c - kOBS)];
      SA[t * SA_LD + pk(c)] = f2tf(v);
    }
  }

  float d4[2][4][4];
  float d2[2][2][4];
  float d1[2][1][4];

  // ======== merged e|eq: [64,256] = sa @ [We;Weq]^T, 16 warps MT2NT4 =====
  zero_acc(d4);
  staged_big<8>(SA, SA_LD, gWP + OPK_EE, d4, W, tid, lane, wm, wn);
  if (wn < 4) {  // cols 0-127 -> e
    for_each_pair<4>(d4, lane, wm, wn, [&](int r, int c, float lo, float hi) {
      int lg = (c & ~7) + ((c & 7) >> 1);
      lo += __ldg(b_embed + lg);
      hi += __ldg(b_embed + lg + 4);
      lo = lo > 0.f ? lo : 0.01f * lo;
      hi = hi > 0.f ? hi : 0.01f * hi;
      *(float2*)(E + r * E_LD + c) = make_float2(f2tf(lo), f2tf(hi));
    });
  } else {  // cols 128-255 -> eq
    for_each_pair<4>(d4, lane, wm, wn, [&](int r, int c, float lo, float hi) {
      int cl = c - 128;
      int lg = (cl & ~7) + ((cl & 7) >> 1);
      lo += __ldg(b_embed_q + lg);
      hi += __ldg(b_embed_q + lg + 4);
      lo = lo > 0.f ? lo : 0.01f * lo;
      hi = hi > 0.f ? hi : 0.01f * hi;
      *(float2*)(EQ + r * E_LD + cl) = make_float2(f2tf(lo), f2tf(hi));
    });
  }
  __syncthreads();  // E/EQ complete; SA dead after this stage's MMAs

  // ======== merged t|v: [64,256] = e @ [Mt;Wv]^T =========================
  zero_acc(d4);
  staged_big<4>(E, E_LD, gWP + OPK_TV, d4, W, tid, lane, wm, wn);
  if (wn < 4) {  // t -> T (SA region, dead)
    for_each_pair<4>(d4, lane, wm, wn, [&](int r, int c, float lo, float hi) {
      *(float2*)(T + r * E_LD + c) = make_float2(f2tf(lo), f2tf(hi));
    });
  } else {  // v -> VT transposed, token-dim packed
    for_each_pair<4>(d4, lane, wm, wn, [&](int r, int c, float lo, float hi) {
      int cl = c - 128;
      int rp = (r & ~7) + pkgr;
      VT[cl * S_LD + rp] = f2tf(lo);
      VT[(cl + 1) * S_LD + rp] = f2tf(hi);
    });
  }
  __syncthreads();  // T, VT visible

  // ======== scores = t @ e^T / sqrt(D) -> SC fp32 (16 warps) =============
  zero_acc(d1);
  mma_block<1, 128>(T, E_LD, E, E_LD, d1, lane, wm, wn);
  for_each_pair<1>(d1, lane, wm, wn, [&](int r, int c, float lo, float hi) {
    *(float2*)(SC + r * S_LD + c) =
        make_float2(lo * 0.08838834764831845f, hi * 0.08838834764831845f);
  });
  __syncthreads();

  // ======== row softmax: gmem fp32 logical + packed tf32 back into SC ====
  {
    const int r = tid >> 3;
    const int c0 = (tid & 7) * 8;
    float* wrow = SC + r * S_LD + c0;
    float s[8];
#pragma unroll
    for (int j = 0; j < 8; j++) s[j] = wrow[j];
    float mx = -3.0e38f;
#pragma unroll
    for (int j = 0; j < 8; j++) mx = fmaxf(mx, s[j]);
    mx = fmaxf(mx, __shfl_xor_sync(0xffffffffu, mx, 1));
    mx = fmaxf(mx, __shfl_xor_sync(0xffffffffu, mx, 2));
    mx = fmaxf(mx, __shfl_xor_sync(0xffffffffu, mx, 4));
    float sum = 0.f;
#pragma unroll
    for (int j = 0; j < 8; j++) {
      s[j] = __expf(s[j] - mx);
      sum += s[j];
    }
    sum += __shfl_xor_sync(0xffffffffu, sum, 1);
    sum += __shfl_xor_sync(0xffffffffu, sum, 2);
    sum += __shfl_xor_sync(0xffffffffu, sum, 4);
    float inv = 1.f / sum;
    float* og = outW + ((size_t)b * kN + r) * kN + c0;
#pragma unroll
    for (int j = 0; j < 8; j++) {
      float wv = s[j] * inv;
      og[j] = wv;
      wrow[2 * (j & 3) + (j >> 2)] = f2tf(wv);
    }
  }
  __syncthreads();

  // ======== x = weight @ v -> E (identity-packed) ========================
  zero_acc(d2);
  mma_block<2, 64>(SC, S_LD, VT, S_LD, d2, lane, wm, wn);
  for_each_pair<2>(d2, lane, wm, wn, [&](int r, int c, float lo, float hi) {
    *(float2*)(E + r * E_LD + c) = make_float2(f2tf(lo), f2tf(hi));
  });
  __syncthreads();  // X done; T dead -> H may reuse SA region later

  // ======== h = lrelu([eq, x] @ W_f1^T)  (accumulate halves) =============
  zero_acc(d1);
  staged_small<4>(EQ, E_LD, gWP + OPK_F1, d1, W, tid, lane, wm, wn);
  staged_small<4>(E, E_LD, gWP + OPK_F1 + 4 * CHS, d1, W, tid, lane, wm, wn);
  for_each_pair<1>(d1, lane, wm, wn, [&](int r, int c, float lo, float hi) {
    lo = lo > 0.f ? lo : 0.01f * lo;
    hi = hi > 0.f ? hi : 0.01f * hi;
    *(float2*)(H + r * S_LD + c) = make_float2(f2tf(lo), f2tf(hi));
  });
  __syncthreads();  // H visible before f2 staging overwrites nothing of it

  // ======== Value = h @ W_f2^T -> gmem (f2 unpermuted -> logical cols) ===
  zero_acc(d1);
  staged_small<2>(H, S_LD, gWP + OPK_F2, d1, W, tid, lane, wm, wn);
  for_each_pair<1>(d1, lane, wm, wn, [&](int r, int c, float lo, float hi) {
    *(float2*)(outV + ((size_t)b * kN + r) * kFO + c) = make_float2(lo, hi);
  });
}

}  // namespace

extern "C" void kernel_launch(void* const* d_in, const int* in_sizes, int n_in,
                              void* d_out, int out_size) {
  (void)in_sizes; (void)n_in; (void)out_size;
  const float* states    = (const float*)d_in[0];
  const float* actions   = (const float*)d_in[1];
  const float* W_embed   = (const float*)d_in[2];
  const float* b_embed   = (const float*)d_in[3];
  const float* W_k       = (const float*)d_in[4];
  const float* W_q       = (const float*)d_in[5];
  const float* W_v       = (const float*)d_in[6];
  const float* W_embed_q = (const float*)d_in[7];
  const float* b_embed_q = (const float*)d_in[8];
  const float* W_f1      = (const float*)d_in[9];
  const float* W_f2      = (const float*)d_in[10];

  float* outV = (float*)d_out;                 // Value [B,N,64]
  float* outW = outV + (size_t)kB * kN * kFO;  // weight [B,N,N]

  precompute_mt<<<kD, kD>>>(W_q, W_k);
  // merged [We;Weq]: 8 chunks of 256 rows
  pack_w<<<(8 * 128 * 32 + 255) / 256, 256>>>(W_embed, 128, kIN, 8, OPK_EE,
                                              256, 0, 1);
  pack_w<<<(8 * 128 * 32 + 255) / 256, 256>>>(W_embed_q, 128, kIN, 8, OPK_EE,
                                              256, 128, 1);
  // merged [Mt;Wv]: Wv into rows 128-255 of 4 chunks (Mt filled by precompute)
  pack_w<<<(4 * 128 * 32 + 255) / 256, 256>>>(W_v, 128, kD, 4, OPK_TV,
                                              256, 128, 1);
  pack_w<<<(8 * 64 * 32 + 255) / 256, 256>>>(W_f1, 64, 2 * kD, 8, OPK_F1,
                                             64, 0, 1);
  pack_w<<<(2 * 64 * 32 + 255) / 256, 256>>>(W_f2, 64, kN, 2, OPK_F2,
                                             64, 0, 0);

  cudaFuncSetAttribute(critic_kernel,
                       cudaFuncAttributeMaxDynamicSharedMemorySize, SMEM_BYTES);
  critic_kernel<<<kB, kThreads, SMEM_BYTES>>>(states, actions, b_embed,
                                              b_embed_q, outV, outW);
}

// round 12
// speedup vs baseline: 1.0906x; 1.0255x over previous
#include <cuda_runtime.h>
#include <cstdint>
#include <cstddef>

namespace {

constexpr int kB   = 4096;
constexpr int kN   = 64;
constexpr int kOBS = 192;
constexpr int kACT = 64;
constexpr int kIN  = 256;
constexpr int kD   = 128;
constexpr int kFO  = 64;

constexpr int kThreads = 512;  // 16 warps

// strides ≡ 8 (mod 32): conflict-free float2 fragment loads
constexpr int SA_LD = 264;
constexpr int E_LD  = 136;
constexpr int S_LD  = 72;
constexpr int WG_LD = 40;

// SMEM pool (floats) — refit for double-buffered big chunks (223232 B total)
//  W0/W1 [2 x 256x40] = 20480 @ 0      (big stage double buffer; small stages
//                                       use sub-buffers; SC aliases @0 during
//                                       scores->softmax->x when staging idle)
//  SAreg 17408 @ 20480: SA [64x264]=16896 during e|eq (dead at stage end);
//                       then EQ [64x136]=8704 @20480, T [64x136]=8704 @29184;
//                       H [64x72] @29184 after T dies.
//  E     [64x136]=8704 @ 37888   (e; later x)
//  VT    [128x72]=9216 @ 46592
constexpr int OFF_W0 = 0;
constexpr int OFF_W1 = 10240;
constexpr int OFF_SC = 0;
constexpr int OFF_SA = 20480;
constexpr int OFF_EQ = 20480;
constexpr int OFF_T  = 29184;
constexpr int OFF_H  = 29184;
constexpr int OFF_E  = 37888;
constexpr int OFF_VT = 46592;
constexpr int SMEM_FLOATS = 55808;
constexpr int SMEM_BYTES  = SMEM_FLOATS * 4;  // 223232 <= 232448 cap

// Pre-packed weights (tf32-rounded, pk k-packing, pk row-perm, SMEM image)
constexpr int CHEE = 256 * WG_LD;  // 10240 per merged 256-row chunk
constexpr int CHS  = 64 * WG_LD;   // 2560 per 64-row chunk
constexpr int OPK_EE = 0;                   // 8 chunks [We;Weq]
constexpr int OPK_TV = 8 * CHEE;            // 4 chunks [Mt;Wv]
constexpr int OPK_F1 = 12 * CHEE;           // 8 chunks (64-row)
constexpr int OPK_F2 = OPK_F1 + 8 * CHS;    // 2 chunks
constexpr int PK_TOTAL = OPK_F2 + 2 * CHS;  // 148480
__device__ float gWP[PK_TOTAL];

__device__ __forceinline__ float f2tf(float x) {
  uint32_t u;
  asm("cvt.rna.tf32.f32 %0, %1;" : "=r"(u) : "f"(x));
  return __uint_as_float(u);
}

// packing within 8-groups: (k, k+4) adjacent
__device__ __forceinline__ int pk(int k) {
  return (k & ~7) + 2 * (k & 3) + ((k >> 2) & 1);
}

__device__ __forceinline__ void mma8(float (&d)[4], const uint32_t (&a)[4],
                                     const uint32_t (&b)[2]) {
  asm volatile(
      "mma.sync.aligned.m16n8k8.row.col.f32.tf32.tf32.f32 "
      "{%0,%1,%2,%3}, {%4,%5,%6,%7}, {%8,%9}, {%0,%1,%2,%3};\n"
      : "+f"(d[0]), "+f"(d[1]), "+f"(d[2]), "+f"(d[3])
      : "r"(a[0]), "r"(a[1]), "r"(a[2]), "r"(a[3]), "r"(b[0]), "r"(b[1]));
}

// R9-R11-proven float2 fragment loads; pk-packed along k.
template <int NT, int KC>
__device__ __forceinline__ void mma_block(const float* __restrict__ As, int lda,
                                          const float* __restrict__ Bs, int ldb,
                                          float (&d)[2][NT][4],
                                          int lane, int wm, int wn) {
  const float* Aw = As + (wm * 32) * lda;
  const float* Bw = Bs + (wn * NT * 8) * ldb;
  const int gr = lane >> 2, gc = lane & 3;
#pragma unroll
  for (int k0 = 0; k0 < KC; k0 += 8) {
    uint32_t a[2][4];
#pragma unroll
    for (int mt = 0; mt < 2; mt++) {
      float2 v0 = *(const float2*)(Aw + (mt * 16 + gr) * lda + k0 + 2 * gc);
      float2 v1 = *(const float2*)(Aw + (mt * 16 + 8 + gr) * lda + k0 + 2 * gc);
      a[mt][0] = __float_as_uint(v0.x);
      a[mt][1] = __float_as_uint(v1.x);
      a[mt][2] = __float_as_uint(v0.y);
      a[mt][3] = __float_as_uint(v1.y);
    }
#pragma unroll
    for (int nt = 0; nt < NT; nt++) {
      float2 bv = *(const float2*)(Bw + (nt * 8 + gr) * ldb + k0 + 2 * gc);
      uint32_t bf[2] = {__float_as_uint(bv.x), __float_as_uint(bv.y)};
      mma8(d[0][nt], a[0], bf);
      mma8(d[1][nt], a[1], bf);
    }
  }
}

// Pair-wise epilogue (proven): cphys is the packed dest index.
template <int NT, class F>
__device__ __forceinline__ void for_each_pair(float (&d)[2][NT][4], int lane,
                                              int wm, int wn, F f) {
  const int gr = lane >> 2;
  const int gc2 = (lane & 3) * 2;
#pragma unroll
  for (int mt = 0; mt < 2; mt++)
#pragma unroll
    for (int nt = 0; nt < NT; nt++) {
      int col = wn * NT * 8 + nt * 8 + gc2;
      int row = wm * 32 + mt * 16 + gr;
      f(row, col, d[mt][nt][0], d[mt][nt][1]);
      f(row + 8, col, d[mt][nt][2], d[mt][nt][3]);
    }
}

template <int NT>
__device__ __forceinline__ void zero_acc(float (&d)[2][NT][4]) {
#pragma unroll
  for (int mt = 0; mt < 2; mt++)
#pragma unroll
    for (int nt = 0; nt < NT; nt++)
#pragma unroll
      for (int i = 0; i < 4; i++) d[mt][nt][i] = 0.f;
}

// ---- cp.async staging of pre-packed chunks (contiguous copies)
__device__ __forceinline__ void cp16(uint32_t saddr, const float* __restrict__ g) {
  asm volatile("cp.async.ca.shared.global [%0], [%1], 16;\n"
               :: "r"(saddr), "l"(g) : "memory");
}
template <int FCNT>
__device__ __forceinline__ void cpa_chunk(float* dst, const float* __restrict__ src,
                                          int tid) {
  uint32_t s0 = (uint32_t)__cvta_generic_to_shared(dst);
#pragma unroll
  for (int i = tid; i < FCNT / 4; i += kThreads)
    cp16(s0 + (uint32_t)i * 16u, src + i * 4);
  asm volatile("cp.async.commit_group;\n" ::: "memory");
}
__device__ __forceinline__ void cpa_wait() {
  asm volatile("cp.async.wait_group 0;\n" ::: "memory");
}

// Double-buffered staged matmul over NCH pre-packed chunks; 1 sync/chunk,
// next chunk's fetch fully overlapped with current chunk's MMAs (R10-proven
// pattern, now applied to the big merged chunks too).
template <int NT, int NCH, int FCNT>
__device__ __forceinline__ void staged_mm(const float* __restrict__ A, int lda,
                                          const float* __restrict__ wsrc,
                                          float (&d)[2][NT][4],
                                          float* w0, float* w1, int tid,
                                          int lane, int wm, int wn) {
  cpa_chunk<FCNT>(w0, wsrc, tid);
  cpa_wait();
  __syncthreads();
#pragma unroll
  for (int c = 0; c < NCH; c++) {
    float* cur = (c & 1) ? w1 : w0;
    float* nxt = (c & 1) ? w0 : w1;
    const bool more = (c + 1 < NCH);
    if (more) cpa_chunk<FCNT>(nxt, wsrc + (c + 1) * FCNT, tid);
    mma_block<NT, 32>(A + c * 32, lda, cur, WG_LD, d, lane, wm, wn);
    if (more) cpa_wait();
    __syncthreads();
  }
}

// ---- prologue A: pack W into merged SMEM-image chunks
__global__ void pack_w(const float* __restrict__ W, int On, int Kfull,
                       int nch, int dst_off, int chunk_rows, int row_base,
                       int rperm) {
  int idx = blockIdx.x * 256 + threadIdx.x;
  int total = nch * On * 32;
  if (idx >= total) return;
  int c = idx / (On * 32);
  int rem = idx - c * (On * 32);
  int o = rem >> 5, k = rem & 31;
  int op = row_base + (rperm ? pk(o) : o);
  gWP[dst_off + c * chunk_rows * WG_LD + op * WG_LD + pk(k)] =
      f2tf(W[o * Kfull + c * 32 + k]);
}

// ---- prologue B: Mt[j][i] = sum_d Wq[d][i]*Wk[d][j] -> rows 0-127 of TV chunks
__global__ void precompute_mt(const float* __restrict__ Wq,
                              const float* __restrict__ Wk) {
  __shared__ float wkj[kD];
  const int j = blockIdx.x;
  const int i = threadIdx.x;
  wkj[i] = Wk[i * kD + j];
  __syncthreads();
  float s = 0.f;
#pragma unroll 8
  for (int dd = 0; dd < kD; dd++) s += Wq[dd * kD + i] * wkj[dd];
  int c = i >> 5, k = i & 31;
  gWP[OPK_TV + c * CHEE + pk(j) * WG_LD + pk(k)] = f2tf(s);
}

__global__ __launch_bounds__(kThreads, 1)
void critic_kernel(const float* __restrict__ states,
                   const float* __restrict__ actions,
                   const float* __restrict__ b_embed,
                   const float* __restrict__ b_embed_q,
                   float* __restrict__ outV,
                   float* __restrict__ outW) {
  extern __shared__ float smem[];
  const int b = blockIdx.x;
  const int tid = threadIdx.x;
  const int lane = tid & 31;
  const int warp = tid >> 5;
  const int wm = warp >> 3, wn = warp & 7;  // 16-warp grid
  const int gr = lane >> 2;
  const int pkgr = 2 * (gr & 3) + ((gr >> 2) & 1);  // pk8(gr)

  float* W0 = smem + OFF_W0;
  float* W1 = smem + OFF_W1;
  float* SC = smem + OFF_SC;
  float* SA = smem + OFF_SA;
  float* EQ = smem + OFF_EQ;
  float* T  = smem + OFF_T;
  float* H  = smem + OFF_H;
  float* E  = smem + OFF_E;
  float* VT = smem + OFF_VT;

  // ---- load sa, pk-packed (first staged sync covers visibility)
  {
    const float* st = states + (size_t)b * kN * kOBS;
    const float* ac = actions + (size_t)b * kN * kACT;
#pragma unroll 4
    for (int j = 0; j < 32; j++) {
      int i = tid + j * kThreads;
      int t = i >> 8, c = i & 255;
      float v = (c < kOBS) ? st[t * kOBS + c] : ac[t * kACT + (c - kOBS)];
      SA[t * SA_LD + pk(c)] = f2tf(v);
    }
  }

  float d4[2][4][4];
  float d2[2][2][4];
  float d1[2][1][4];

  // ======== merged e|eq: [64,256] = sa @ [We;Weq]^T (double-buffered) ====
  // All MMAs complete at staged_mm's final barrier, so the EQ epilogue may
  // safely overwrite the (now dead) SA region.
  zero_acc(d4);
  staged_mm<4, 8, CHEE>(SA, SA_LD, gWP + OPK_EE, d4, W0, W1, tid, lane, wm, wn);
  if (wn < 4) {  // cols 0-127 -> e
    for_each_pair<4>(d4, lane, wm, wn, [&](int r, int c, float lo, float hi) {
      int lg = (c & ~7) + ((c & 7) >> 1);
      lo += __ldg(b_embed + lg);
      hi += __ldg(b_embed + lg + 4);
      lo = lo > 0.f ? lo : 0.01f * lo;
      hi = hi > 0.f ? hi : 0.01f * hi;
      *(float2*)(E + r * E_LD + c) = make_float2(f2tf(lo), f2tf(hi));
    });
  } else {  // cols 128-255 -> eq (into dead-SA region)
    for_each_pair<4>(d4, lane, wm, wn, [&](int r, int c, float lo, float hi) {
      int cl = c - 128;
      int lg = (cl & ~7) + ((cl & 7) >> 1);
      lo += __ldg(b_embed_q + lg);
      hi += __ldg(b_embed_q + lg + 4);
      lo = lo > 0.f ? lo : 0.01f * lo;
      hi = hi > 0.f ? hi : 0.01f * hi;
      *(float2*)(EQ + r * E_LD + cl) = make_float2(f2tf(lo), f2tf(hi));
    });
  }
  __syncthreads();  // E/EQ complete

  // ======== merged t|v: [64,256] = e @ [Mt;Wv]^T (double-buffered) =======
  zero_acc(d4);
  staged_mm<4, 4, CHEE>(E, E_LD, gWP + OPK_TV, d4, W0, W1, tid, lane, wm, wn);
  if (wn < 4) {  // t -> T
    for_each_pair<4>(d4, lane, wm, wn, [&](int r, int c, float lo, float hi) {
      *(float2*)(T + r * E_LD + c) = make_float2(f2tf(lo), f2tf(hi));
    });
  } else {  // v -> VT transposed, token-dim packed
    for_each_pair<4>(d4, lane, wm, wn, [&](int r, int c, float lo, float hi) {
      int cl = c - 128;
      int rp = (r & ~7) + pkgr;
      VT[cl * S_LD + rp] = f2tf(lo);
      VT[(cl + 1) * S_LD + rp] = f2tf(hi);
    });
  }
  __syncthreads();  // T, VT visible; W buffers now idle -> SC may alias

  // ======== scores = t @ e^T / sqrt(D) -> SC fp32 (in W region) ==========
  zero_acc(d1);
  mma_block<1, 128>(T, E_LD, E, E_LD, d1, lane, wm, wn);
  for_each_pair<1>(d1, lane, wm, wn, [&](int r, int c, float lo, float hi) {
    *(float2*)(SC + r * S_LD + c) =
        make_float2(lo * 0.08838834764831845f, hi * 0.08838834764831845f);
  });
  __syncthreads();

  // ======== row softmax: gmem fp32 logical + packed tf32 back into SC ====
  {
    const int r = tid >> 3;
    const int c0 = (tid & 7) * 8;
    float* wrow = SC + r * S_LD + c0;
    float s[8];
#pragma unroll
    for (int j = 0; j < 8; j++) s[j] = wrow[j];
    float mx = -3.0e38f;
#pragma unroll
    for (int j = 0; j < 8; j++) mx = fmaxf(mx, s[j]);
    mx = fmaxf(mx, __shfl_xor_sync(0xffffffffu, mx, 1));
    mx = fmaxf(mx, __shfl_xor_sync(0xffffffffu, mx, 2));
    mx = fmaxf(mx, __shfl_xor_sync(0xffffffffu, mx, 4));
    float sum = 0.f;
#pragma unroll
    for (int j = 0; j < 8; j++) {
      s[j] = __expf(s[j] - mx);
      sum += s[j];
    }
    sum += __shfl_xor_sync(0xffffffffu, sum, 1);
    sum += __shfl_xor_sync(0xffffffffu, sum, 2);
    sum += __shfl_xor_sync(0xffffffffu, sum, 4);
    float inv = 1.f / sum;
    float* og = outW + ((size_t)b * kN + r) * kN + c0;
#pragma unroll
    for (int j = 0; j < 8; j++) {
      float wv = s[j] * inv;
      og[j] = wv;
      wrow[2 * (j & 3) + (j >> 2)] = f2tf(wv);
    }
  }
  __syncthreads();

  // ======== x = weight @ v -> E (identity-packed) ========================
  zero_acc(d2);
  mma_block<2, 64>(SC, S_LD, VT, S_LD, d2, lane, wm, wn);
  for_each_pair<2>(d2, lane, wm, wn, [&](int r, int c, float lo, float hi) {
    *(float2*)(E + r * E_LD + c) = make_float2(f2tf(lo), f2tf(hi));
  });
  __syncthreads();  // x done; SC (=W region) dead -> staging may resume

  // ======== h = lrelu([eq, x] @ W_f1^T)  (accumulate halves) =============
  zero_acc(d1);
  staged_mm<1, 4, CHS>(EQ, E_LD, gWP + OPK_F1, d1, W0, W0 + 5120, tid, lane,
                       wm, wn);
  staged_mm<1, 4, CHS>(E, E_LD, gWP + OPK_F1 + 4 * CHS, d1, W0, W0 + 5120,
                       tid, lane, wm, wn);
  for_each_pair<1>(d1, lane, wm, wn, [&](int r, int c, float lo, float hi) {
    lo = lo > 0.f ? lo : 0.01f * lo;
    hi = hi > 0.f ? hi : 0.01f * hi;
    *(float2*)(H + r * S_LD + c) = make_float2(f2tf(lo), f2tf(hi));  // T dead
  });

  // ======== Value = h @ W_f2^T -> gmem (f2 unpermuted -> logical cols) ===
  // (staged_mm's first barrier orders the H writes before the MMAs)
  zero_acc(d1);
  staged_mm<1, 2, CHS>(H, S_LD, gWP + OPK_F2, d1, W0, W0 + 5120, tid, lane,
                       wm, wn);
  for_each_pair<1>(d1, lane, wm, wn, [&](int r, int c, float lo, float hi) {
    *(float2*)(outV + ((size_t)b * kN + r) * kFO + c) = make_float2(lo, hi);
  });
}

}  // namespace

extern "C" void kernel_launch(void* const* d_in, const int* in_sizes, int n_in,
                              void* d_out, int out_size) {
  (void)in_sizes; (void)n_in; (void)out_size;
  const float* states    = (const float*)d_in[0];
  const float* actions   = (const float*)d_in[1];
  const float* W_embed   = (const float*)d_in[2];
  const float* b_embed   = (const float*)d_in[3];
  const float* W_k       = (const float*)d_in[4];
  const float* W_q       = (const float*)d_in[5];
  const float* W_v       = (const float*)d_in[6];
  const float* W_embed_q = (const float*)d_in[7];
  const float* b_embed_q = (const float*)d_in[8];
  const float* W_f1      = (const float*)d_in[9];
  const float* W_f2      = (const float*)d_in[10];

  float* outV = (float*)d_out;                 // Value [B,N,64]
  float* outW = outV + (size_t)kB * kN * kFO;  // weight [B,N,N]

  precompute_mt<<<kD, kD>>>(W_q, W_k);
  pack_w<<<(8 * 128 * 32 + 255) / 256, 256>>>(W_embed, 128, kIN, 8, OPK_EE,
                                              256, 0, 1);
  pack_w<<<(8 * 128 * 32 + 255) / 256, 256>>>(W_embed_q, 128, kIN, 8, OPK_EE,
                                              256, 128, 1);
  pack_w<<<(4 * 128 * 32 + 255) / 256, 256>>>(W_v, 128, kD, 4, OPK_TV,
                                              256, 128, 1);
  pack_w<<<(8 * 64 * 32 + 255) / 256, 256>>>(W_f1, 64, 2 * kD, 8, OPK_F1,
                                             64, 0, 1);
  pack_w<<<(2 * 64 * 32 + 255) / 256, 256>>>(W_f2, 64, kN, 2, OPK_F2,
                                             64, 0, 0);

  cudaFuncSetAttribute(critic_kernel,
                       cudaFuncAttributeMaxDynamicSharedMemorySize, SMEM_BYTES);
  critic_kernel<<<kB, kThreads, SMEM_BYTES>>>(states, actions, b_embed,
                                              b_embed_q, outV, outW);
}

// round 13
// speedup vs baseline: 2.1630x; 1.9832x over previous
#include <cuda_runtime.h>
#include <cuda_fp16.h>
#include <cstdint>
#include <cstddef>

namespace {

constexpr int kB   = 4096;
constexpr int kN   = 64;
constexpr int kOBS = 192;
constexpr int kACT = 64;
constexpr int kIN  = 256;
constexpr int kD   = 128;
constexpr int kFO  = 64;

constexpr int kThreads = 512;  // 16 warps; 2 CTAs per SM

// strides in __half units; word-step (stride/2 mod 32) ∈ {4,20} -> conflict-free
constexpr int SA_LD = 264;  // 132w step -> 4
constexpr int E_LD  = 136;  // 68w -> 4
constexpr int S_LD  = 72;   // 36w -> 4
constexpr int WG_LD = 40;   // 20w -> 20 (injective)

// SMEM pool (__half units), total 55808 h = 111616 B -> 2 CTAs/SM
//  W0 @0 (10240), W1 @10240 (10240)   [SC fp32 aliases W0; SCH fp16 aliases W1]
//  SA region @20480 (17920): SA 64x264=16896 during e|eq;
//     then T 64x136=8704 @20480 + VT 128x72=9216 @29184; H 64x72 @20480 later
//  E @38400 (8704)  (e; later x)
//  EQ @47104 (8704)
constexpr int OFF_W0 = 0;
constexpr int OFF_W1 = 10240;
constexpr int OFF_SA = 20480;
constexpr int OFF_T  = 20480;
constexpr int OFF_VT = 29184;
constexpr int OFF_H  = 20480;
constexpr int OFF_E  = 38400;
constexpr int OFF_EQ = 47104;
constexpr int SMEM_HALVES = 55808;
constexpr int SMEM_BYTES  = SMEM_HALVES * 2;  // 111616

// Pre-packed fp16 weights (SMEM-image chunks of K=32)
constexpr int CHEE = 256 * WG_LD;  // 10240 halves per merged 256-row chunk
constexpr int CHS  = 64 * WG_LD;   // 2560 halves per 64-row chunk
constexpr int OPK_EE = 0;                   // 8 chunks [We;Weq]
constexpr int OPK_TV = 8 * CHEE;            // 4 chunks [Mt;Wv]
constexpr int OPK_F1 = 12 * CHEE;           // 8 chunks (64-row)
constexpr int OPK_F2 = OPK_F1 + 8 * CHS;    // 2 chunks
constexpr int PK_TOTAL = OPK_F2 + 2 * CHS;  // 148480 halves
__device__ __half gWP[PK_TOTAL];

__device__ __forceinline__ void mma16(float (&d)[4], const uint32_t (&a)[4],
                                      const uint32_t (&b)[2]) {
  asm volatile(
      "mma.sync.aligned.m16n8k16.row.col.f32.f16.f16.f32 "
      "{%0,%1,%2,%3}, {%4,%5,%6,%7}, {%8,%9}, {%0,%1,%2,%3};\n"
      : "+f"(d[0]), "+f"(d[1]), "+f"(d[2]), "+f"(d[3])
      : "r"(a[0]), "r"(a[1]), "r"(a[2]), "r"(a[3]), "r"(b[0]), "r"(b[1]));
}

// C[64 rows][NT*8 cols per warp] += A[64][KC] * B[cols][KC]^T, fp16 inputs.
// m16n8k16 fragments (natural fp16x2 adjacency, no permutation):
//  a0=A[gr][2gc:+1], a1=A[gr+8][2gc:+1], a2=A[gr][2gc+8:+9], a3=A[gr+8][2gc+8:+9]
//  b0=Bt[n=gr][2gc:+1], b1=Bt[n=gr][2gc+8:+9]
template <int NT, int KC>
__device__ __forceinline__ void mma_block(const __half* __restrict__ As, int lda,
                                          const __half* __restrict__ Bs, int ldb,
                                          float (&d)[2][NT][4],
                                          int lane, int wm, int wn) {
  const __half* Aw = As + (wm * 32) * lda;
  const __half* Bw = Bs + (wn * NT * 8) * ldb;
  const int gr = lane >> 2, gc = lane & 3;
#pragma unroll
  for (int k0 = 0; k0 < KC; k0 += 16) {
    uint32_t a[2][4];
#pragma unroll
    for (int mt = 0; mt < 2; mt++) {
      const __half* p = Aw + (mt * 16 + gr) * lda + k0 + 2 * gc;
      a[mt][0] = *(const uint32_t*)(p);
      a[mt][1] = *(const uint32_t*)(p + 8 * lda);
      a[mt][2] = *(const uint32_t*)(p + 8);
      a[mt][3] = *(const uint32_t*)(p + 8 * lda + 8);
    }
#pragma unroll
    for (int nt = 0; nt < NT; nt++) {
      const __half* p = Bw + (nt * 8 + gr) * ldb + k0 + 2 * gc;
      uint32_t b[2] = {*(const uint32_t*)(p), *(const uint32_t*)(p + 8)};
      mma16(d[0][nt], a[0], b);
      mma16(d[1][nt], a[1], b);
    }
  }
}

// Pair epilogue: f(row, c, lo, hi) for fp32 pair at LOGICAL cols (c, c+1).
template <int NT, class F>
__device__ __forceinline__ void for_each_pair(float (&d)[2][NT][4], int lane,
                                              int wm, int wn, F f) {
  const int gr = lane >> 2;
  const int gc2 = (lane & 3) * 2;
#pragma unroll
  for (int mt = 0; mt < 2; mt++)
#pragma unroll
    for (int nt = 0; nt < NT; nt++) {
      int col = wn * NT * 8 + nt * 8 + gc2;
      int row = wm * 32 + mt * 16 + gr;
      f(row, col, d[mt][nt][0], d[mt][nt][1]);
      f(row + 8, col, d[mt][nt][2], d[mt][nt][3]);
    }
}

template <int NT>
__device__ __forceinline__ void zero_acc(float (&d)[2][NT][4]) {
#pragma unroll
  for (int mt = 0; mt < 2; mt++)
#pragma unroll
    for (int nt = 0; nt < NT; nt++)
#pragma unroll
      for (int i = 0; i < 4; i++) d[mt][nt][i] = 0.f;
}

// ---- cp.async staging of pre-packed fp16 chunks (contiguous)
__device__ __forceinline__ void cp16b(uint32_t saddr, const void* __restrict__ g) {
  asm volatile("cp.async.ca.shared.global [%0], [%1], 16;\n"
               :: "r"(saddr), "l"(g) : "memory");
}
template <int HCNT>
__device__ __forceinline__ void cpa_chunk(__half* dst, const __half* __restrict__ src,
                                          int tid) {
  uint32_t s0 = (uint32_t)__cvta_generic_to_shared(dst);
#pragma unroll
  for (int i = tid; i < HCNT / 8; i += kThreads)
    cp16b(s0 + (uint32_t)i * 16u, src + i * 8);
  asm volatile("cp.async.commit_group;\n" ::: "memory");
}
__device__ __forceinline__ void cpa_wait() {
  asm volatile("cp.async.wait_group 0;\n" ::: "memory");
}

// Double-buffered staged matmul (R12-proven): 1 sync/chunk, fetch overlapped.
template <int NT, int NCH, int HCNT>
__device__ __forceinline__ void staged_mm(const __half* __restrict__ A, int lda,
                                          const __half* __restrict__ wsrc,
                                          float (&d)[2][NT][4],
                                          __half* w0, __half* w1, int tid,
                                          int lane, int wm, int wn) {
  cpa_chunk<HCNT>(w0, wsrc, tid);
  cpa_wait();
  __syncthreads();
#pragma unroll
  for (int c = 0; c < NCH; c++) {
    __half* cur = (c & 1) ? w1 : w0;
    __half* nxt = (c & 1) ? w0 : w1;
    const bool more = (c + 1 < NCH);
    if (more) cpa_chunk<HCNT>(nxt, wsrc + (c + 1) * HCNT, tid);
    mma_block<NT, 32>(A + c * 32, lda, cur, WG_LD, d, lane, wm, wn);
    if (more) cpa_wait();
    __syncthreads();
  }
}

// ---- prologue A: pack fp32 weights -> fp16 SMEM-image chunks (no perms)
__global__ void pack_w(const float* __restrict__ W, int On, int Kfull,
                       int nch, int dst_off, int chunk_rows, int row_base) {
  int idx = blockIdx.x * 256 + threadIdx.x;
  int total = nch * On * 32;
  if (idx >= total) return;
  int c = idx / (On * 32);
  int rem = idx - c * (On * 32);
  int o = rem >> 5, k = rem & 31;
  gWP[dst_off + c * chunk_rows * WG_LD + (row_base + o) * WG_LD + k] =
      __float2half_rn(W[o * Kfull + c * 32 + k]);
}

// ---- prologue B: Mt[j][i] = sum_d Wq[d][i]*Wk[d][j] -> rows 0-127 of TV chunks
__global__ void precompute_mt(const float* __restrict__ Wq,
                              const float* __restrict__ Wk) {
  __shared__ float wkj[kD];
  const int j = blockIdx.x;
  const int i = threadIdx.x;
  wkj[i] = Wk[i * kD + j];
  __syncthreads();
  float s = 0.f;
#pragma unroll 8
  for (int dd = 0; dd < kD; dd++) s += Wq[dd * kD + i] * wkj[dd];
  int c = i >> 5, k = i & 31;
  gWP[OPK_TV + c * CHEE + j * WG_LD + k] = __float2half_rn(s);
}

__global__ __launch_bounds__(kThreads, 2)
void critic_kernel(const float* __restrict__ states,
                   const float* __restrict__ actions,
                   const float* __restrict__ b_embed,
                   const float* __restrict__ b_embed_q,
                   float* __restrict__ outV,
                   float* __restrict__ outW) {
  extern __shared__ __half smem[];
  const int b = blockIdx.x;
  const int tid = threadIdx.x;
  const int lane = tid & 31;
  const int warp = tid >> 5;
  const int wm = warp >> 3, wn = warp & 7;  // 16-warp grid

  __half* W0 = smem + OFF_W0;
  __half* W1 = smem + OFF_W1;
  float*  SCf = reinterpret_cast<float*>(smem + OFF_W0);  // fp32 scores in W0
  __half* SCH = smem + OFF_W1;                            // fp16 weights in W1
  __half* SA = smem + OFF_SA;
  __half* T  = smem + OFF_T;
  __half* VT = smem + OFF_VT;
  __half* H  = smem + OFF_H;
  __half* E  = smem + OFF_E;
  __half* EQ = smem + OFF_EQ;

  // ---- load sa as fp16 (first staged sync covers visibility)
  {
    const float* st = states + (size_t)b * kN * kOBS;
    const float* ac = actions + (size_t)b * kN * kACT;
#pragma unroll 4
    for (int j = 0; j < 32; j++) {
      int i = tid + j * kThreads;
      int t = i >> 8, c = i & 255;
      float v = (c < kOBS) ? st[t * kOBS + c] : ac[t * kACT + (c - kOBS)];
      SA[t * SA_LD + c] = __float2half_rn(v);
    }
  }

  float d4[2][4][4];
  float d2[2][2][4];
  float d1[2][1][4];

  // ======== merged e|eq: [64,256] = sa @ [We;Weq]^T (double-buffered) ====
  zero_acc(d4);
  staged_mm<4, 8, CHEE>(SA, SA_LD, gWP + OPK_EE, d4, W0, W1, tid, lane, wm, wn);
  if (wn < 4) {  // cols 0-127 -> e
    for_each_pair<4>(d4, lane, wm, wn, [&](int r, int c, float lo, float hi) {
      lo += __ldg(b_embed + c);
      hi += __ldg(b_embed + c + 1);
      lo = lo > 0.f ? lo : 0.01f * lo;
      hi = hi > 0.f ? hi : 0.01f * hi;
      *(__half2*)(E + r * E_LD + c) = __floats2half2_rn(lo, hi);
    });
  } else {  // cols 128-255 -> eq
    for_each_pair<4>(d4, lane, wm, wn, [&](int r, int c, float lo, float hi) {
      int cl = c - 128;
      lo += __ldg(b_embed_q + cl);
      hi += __ldg(b_embed_q + cl + 1);
      lo = lo > 0.f ? lo : 0.01f * lo;
      hi = hi > 0.f ? hi : 0.01f * hi;
      *(__half2*)(EQ + r * E_LD + cl) = __floats2half2_rn(lo, hi);
    });
  }
  __syncthreads();  // E/EQ complete; SA dead

  // ======== merged t|v: [64,256] = e @ [Mt;Wv]^T (double-buffered) =======
  zero_acc(d4);
  staged_mm<4, 4, CHEE>(E, E_LD, gWP + OPK_TV, d4, W0, W1, tid, lane, wm, wn);
  if (wn < 4) {  // t -> T (dead SA region)
    for_each_pair<4>(d4, lane, wm, wn, [&](int r, int c, float lo, float hi) {
      *(__half2*)(T + r * E_LD + c) = __floats2half2_rn(lo, hi);
    });
  } else {  // v -> VT transposed [dim][token]
    for_each_pair<4>(d4, lane, wm, wn, [&](int r, int c, float lo, float hi) {
      int cl = c - 128;
      VT[cl * S_LD + r] = __float2half_rn(lo);
      VT[(cl + 1) * S_LD + r] = __float2half_rn(hi);
    });
  }
  __syncthreads();  // T, VT visible; W buffers idle -> SCf may alias W0

  // ======== scores = t @ e^T / sqrt(D) -> SCf fp32 (in W0) ===============
  zero_acc(d1);
  mma_block<1, 128>(T, E_LD, E, E_LD, d1, lane, wm, wn);
  for_each_pair<1>(d1, lane, wm, wn, [&](int r, int c, float lo, float hi) {
    *(float2*)(SCf + r * S_LD + c) =
        make_float2(lo * 0.08838834764831845f, hi * 0.08838834764831845f);
  });
  __syncthreads();

  // ======== row softmax: gmem fp32 + fp16 copy into SCH (W1) =============
  {
    const int r = tid >> 3;
    const int c0 = (tid & 7) * 8;
    const float* wrow = SCf + r * S_LD + c0;
    float s[8];
#pragma unroll
    for (int j = 0; j < 8; j++) s[j] = wrow[j];
    float mx = -3.0e38f;
#pragma unroll
    for (int j = 0; j < 8; j++) mx = fmaxf(mx, s[j]);
    mx = fmaxf(mx, __shfl_xor_sync(0xffffffffu, mx, 1));
    mx = fmaxf(mx, __shfl_xor_sync(0xffffffffu, mx, 2));
    mx = fmaxf(mx, __shfl_xor_sync(0xffffffffu, mx, 4));
    float sum = 0.f;
#pragma unroll
    for (int j = 0; j < 8; j++) {
      s[j] = __expf(s[j] - mx);
      sum += s[j];
    }
    sum += __shfl_xor_sync(0xffffffffu, sum, 1);
    sum += __shfl_xor_sync(0xffffffffu, sum, 2);
    sum += __shfl_xor_sync(0xffffffffu, sum, 4);
    float inv = 1.f / sum;
    float* og = outW + ((size_t)b * kN + r) * kN + c0;
#pragma unroll
    for (int j = 0; j < 8; j++) {
      float wv = s[j] * inv;
      og[j] = wv;
      SCH[r * S_LD + c0 + j] = __float2half_rn(wv);
    }
  }
  __syncthreads();

  // ======== x = weight @ v -> E (e dead after scores) ====================
  zero_acc(d2);
  mma_block<2, 64>(SCH, S_LD, VT, S_LD, d2, lane, wm, wn);
  for_each_pair<2>(d2, lane, wm, wn, [&](int r, int c, float lo, float hi) {
    *(__half2*)(E + r * E_LD + c) = __floats2half2_rn(lo, hi);
  });
  __syncthreads();  // x done; SCf/SCH (=W region) dead -> staging resumes

  // ======== h = lrelu([eq, x] @ W_f1^T)  (accumulate halves) =============
  zero_acc(d1);
  staged_mm<1, 4, CHS>(EQ, E_LD, gWP + OPK_F1, d1, W0, W0 + 5120, tid, lane,
                       wm, wn);
  staged_mm<1, 4, CHS>(E, E_LD, gWP + OPK_F1 + 4 * CHS, d1, W0, W0 + 5120,
                       tid, lane, wm, wn);
  for_each_pair<1>(d1, lane, wm, wn, [&](int r, int c, float lo, float hi) {
    lo = lo > 0.f ? lo : 0.01f * lo;
    hi = hi > 0.f ? hi : 0.01f * hi;
    *(__half2*)(H + r * S_LD + c) = __floats2half2_rn(lo, hi);  // T dead
  });

  // ======== Value = h @ W_f2^T -> gmem ===================================
  zero_acc(d1);
  staged_mm<1, 2, CHS>(H, S_LD, gWP + OPK_F2, d1, W0, W0 + 5120, tid, lane,
                       wm, wn);
  for_each_pair<1>(d1, lane, wm, wn, [&](int r, int c, float lo, float hi) {
    *(float2*)(outV + ((size_t)b * kN + r) * kFO + c) = make_float2(lo, hi);
  });
}

}  // namespace

extern "C" void kernel_launch(void* const* d_in, const int* in_sizes, int n_in,
                              void* d_out, int out_size) {
  (void)in_sizes; (void)n_in; (void)out_size;
  const float* states    = (const float*)d_in[0];
  const float* actions   = (const float*)d_in[1];
  const float* W_embed   = (const float*)d_in[2];
  const float* b_embed   = (const float*)d_in[3];
  const float* W_k       = (const float*)d_in[4];
  const float* W_q       = (const float*)d_in[5];
  const float* W_v       = (const float*)d_in[6];
  const float* W_embed_q = (const float*)d_in[7];
  const float* b_embed_q = (const float*)d_in[8];
  const float* W_f1      = (const float*)d_in[9];
  const float* W_f2      = (const float*)d_in[10];

  float* outV = (float*)d_out;                 // Value [B,N,64]
  float* outW = outV + (size_t)kB * kN * kFO;  // weight [B,N,N]

  precompute_mt<<<kD, kD>>>(W_q, W_k);
  pack_w<<<(8 * 128 * 32 + 255) / 256, 256>>>(W_embed, 128, kIN, 8, OPK_EE,
                                              256, 0);
  pack_w<<<(8 * 128 * 32 + 255) / 256, 256>>>(W_embed_q, 128, kIN, 8, OPK_EE,
                                              256, 128);
  pack_w<<<(4 * 128 * 32 + 255) / 256, 256>>>(W_v, 128, kD, 4, OPK_TV,
                                              256, 128);
  pack_w<<<(8 * 64 * 32 + 255) / 256, 256>>>(W_f1, 64, 2 * kD, 8, OPK_F1,
                                             64, 0);
  pack_w<<<(2 * 64 * 32 + 255) / 256, 256>>>(W_f2, 64, kN, 2, OPK_F2,
                                             64, 0);

  cudaFuncSetAttribute(critic_kernel,
                       cudaFuncAttributeMaxDynamicSharedMemorySize, SMEM_BYTES);
  critic_kernel<<<kB, kThreads, SMEM_BYTES>>>(states, actions, b_embed,
                                              b_embed_q, outV, outW);
}

// round 14
// speedup vs baseline: 2.2643x; 1.0469x over previous
#include <cuda_runtime.h>
#include <cuda_fp16.h>
#include <cstdint>
#include <cstddef>

namespace {

constexpr int kB   = 4096;
constexpr int kN   = 64;
constexpr int kOBS = 192;
constexpr int kACT = 64;
constexpr int kIN  = 256;
constexpr int kD   = 128;
constexpr int kFO  = 64;

constexpr int kThreads = 512;  // 16 warps; 2 CTAs per SM

// strides in __half units; word-step (stride/2 mod 32) ∈ {4,20} -> conflict-free
constexpr int SA_LD = 264;
constexpr int E_LD  = 136;
constexpr int S_LD  = 72;
constexpr int WG_LD = 40;

// SMEM pool (__half units), total 55808 h = 111616 B -> 2 CTAs/SM
constexpr int OFF_W0 = 0;
constexpr int OFF_W1 = 10240;
constexpr int OFF_SA = 20480;
constexpr int OFF_T  = 20480;
constexpr int OFF_VT = 29184;
constexpr int OFF_H  = 20480;
constexpr int OFF_E  = 38400;
constexpr int OFF_EQ = 47104;
constexpr int SMEM_HALVES = 55808;
constexpr int SMEM_BYTES  = SMEM_HALVES * 2;  // 111616

// Pre-packed fp16 weights (SMEM-image chunks of K=32)
constexpr int CHEE = 256 * WG_LD;
constexpr int CHS  = 64 * WG_LD;
constexpr int OPK_EE = 0;
constexpr int OPK_TV = 8 * CHEE;
constexpr int OPK_F1 = 12 * CHEE;
constexpr int OPK_F2 = OPK_F1 + 8 * CHS;
constexpr int PK_TOTAL = OPK_F2 + 2 * CHS;
__device__ __half gWP[PK_TOTAL];

__device__ __forceinline__ void mma16(float (&d)[4], const uint32_t (&a)[4],
                                      const uint32_t (&b)[2]) {
  asm volatile(
      "mma.sync.aligned.m16n8k16.row.col.f32.f16.f16.f32 "
      "{%0,%1,%2,%3}, {%4,%5,%6,%7}, {%8,%9}, {%0,%1,%2,%3};\n"
      : "+f"(d[0]), "+f"(d[1]), "+f"(d[2]), "+f"(d[3])
      : "r"(a[0]), "r"(a[1]), "r"(a[2]), "r"(a[3]), "r"(b[0]), "r"(b[1]));
}

__device__ __forceinline__ void ldsm_x4(uint32_t (&r)[4], uint32_t addr) {
  asm volatile(
      "ldmatrix.sync.aligned.m8n8.x4.shared.b16 {%0,%1,%2,%3}, [%4];"
      : "=r"(r[0]), "=r"(r[1]), "=r"(r[2]), "=r"(r[3]) : "r"(addr));
}
__device__ __forceinline__ void ldsm_x2(uint32_t (&r)[2], uint32_t addr) {
  asm volatile(
      "ldmatrix.sync.aligned.m8n8.x2.shared.b16 {%0,%1}, [%2];"
      : "=r"(r[0]), "=r"(r[1]) : "r"(addr));
}

// C[64 rows][NT*8 cols per warp] += A[64][KC] * B[cols][KC]^T, fp16 inputs,
// fragments via ldmatrix. Lane-address derivation (verified vs PTX spec):
//  A x4: lanes 0-15 -> rows 0-15 @ k0 (R0=rows0-7/k0-7, R1=rows8-15/k0-7),
//        lanes 16-31 -> rows 0-15 @ k0+8 (R2, R3)  == a0..a3 of m16n8k16.
//  B x4: lane groups (0-7,8-15,16-23,24-31) -> (n0-7,k0),(n0-7,k8),
//        (n8-15,k0),(n8-15,k8) => R0,R1 = b of nt; R2,R3 = b of nt+1.
template <int NT, int KC>
__device__ __forceinline__ void mma_block(const __half* __restrict__ As, int lda,
                                          const __half* __restrict__ Bs, int ldb,
                                          float (&d)[2][NT][4],
                                          int lane, int wm, int wn) {
  const __half* Aw = As + (wm * 32) * lda;
  const __half* Bw = Bs + (wn * NT * 8) * ldb;
  const int l15 = lane & 15;
  const int ak = (lane >> 4) << 3;                 // A k-offset per lane half
  uint32_t a0ad = (uint32_t)__cvta_generic_to_shared(Aw + l15 * lda + ak);
  uint32_t a1ad = a0ad + (uint32_t)(16 * lda * sizeof(__half));
  const int bg = lane >> 3;
  const int brow = (lane & 7) + ((bg >> 1) << 3);  // n row within 16-group
  const int bk = (bg & 1) << 3;                    // k offset within 16
  uint32_t b0ad = (uint32_t)__cvta_generic_to_shared(Bw + brow * ldb + bk);
#pragma unroll
  for (int k0 = 0; k0 < KC; k0 += 16) {
    uint32_t a[2][4];
    ldsm_x4(a[0], a0ad + (uint32_t)(k0 * 2));
    ldsm_x4(a[1], a1ad + (uint32_t)(k0 * 2));
    if constexpr (NT == 1) {
      uint32_t bq[2];
      ldsm_x2(bq, b0ad + (uint32_t)(k0 * 2));
      mma16(d[0][0], a[0], bq);
      mma16(d[1][0], a[1], bq);
    } else {
#pragma unroll
      for (int np = 0; np < NT; np += 2) {
        uint32_t bq[4];
        ldsm_x4(bq, b0ad + (uint32_t)((np * 8 * ldb + k0) * 2));
        uint32_t blo[2] = {bq[0], bq[1]};
        uint32_t bhi[2] = {bq[2], bq[3]};
        mma16(d[0][np], a[0], blo);
        mma16(d[1][np], a[1], blo);
        mma16(d[0][np + 1], a[0], bhi);
        mma16(d[1][np + 1], a[1], bhi);
      }
    }
  }
}

// Pair epilogue: f(row, c, lo, hi) for fp32 pair at LOGICAL cols (c, c+1).
template <int NT, class F>
__device__ __forceinline__ void for_each_pair(float (&d)[2][NT][4], int lane,
                                              int wm, int wn, F f) {
  const int gr = lane >> 2;
  const int gc2 = (lane & 3) * 2;
#pragma unroll
  for (int mt = 0; mt < 2; mt++)
#pragma unroll
    for (int nt = 0; nt < NT; nt++) {
      int col = wn * NT * 8 + nt * 8 + gc2;
      int row = wm * 32 + mt * 16 + gr;
      f(row, col, d[mt][nt][0], d[mt][nt][1]);
      f(row + 8, col, d[mt][nt][2], d[mt][nt][3]);
    }
}

template <int NT>
__device__ __forceinline__ void zero_acc(float (&d)[2][NT][4]) {
#pragma unroll
  for (int mt = 0; mt < 2; mt++)
#pragma unroll
    for (int nt = 0; nt < NT; nt++)
#pragma unroll
      for (int i = 0; i < 4; i++) d[mt][nt][i] = 0.f;
}

// ---- cp.async staging of pre-packed fp16 chunks (contiguous)
__device__ __forceinline__ void cp16b(uint32_t saddr, const void* __restrict__ g) {
  asm volatile("cp.async.ca.shared.global [%0], [%1], 16;\n"
               :: "r"(saddr), "l"(g) : "memory");
}
template <int HCNT>
__device__ __forceinline__ void cpa_chunk(__half* dst, const __half* __restrict__ src,
                                          int tid) {
  uint32_t s0 = (uint32_t)__cvta_generic_to_shared(dst);
#pragma unroll
  for (int i = tid; i < HCNT / 8; i += kThreads)
    cp16b(s0 + (uint32_t)i * 16u, src + i * 8);
  asm volatile("cp.async.commit_group;\n" ::: "memory");
}
__device__ __forceinline__ void cpa_wait() {
  asm volatile("cp.async.wait_group 0;\n" ::: "memory");
}

// Double-buffered staged matmul (R12/R13-proven): 1 sync/chunk.
template <int NT, int NCH, int HCNT>
__device__ __forceinline__ void staged_mm(const __half* __restrict__ A, int lda,
                                          const __half* __restrict__ wsrc,
                                          float (&d)[2][NT][4],
                                          __half* w0, __half* w1, int tid,
                                          int lane, int wm, int wn) {
  cpa_chunk<HCNT>(w0, wsrc, tid);
  cpa_wait();
  __syncthreads();
#pragma unroll
  for (int c = 0; c < NCH; c++) {
    __half* cur = (c & 1) ? w1 : w0;
    __half* nxt = (c & 1) ? w0 : w1;
    const bool more = (c + 1 < NCH);
    if (more) cpa_chunk<HCNT>(nxt, wsrc + (c + 1) * HCNT, tid);
    mma_block<NT, 32>(A + c * 32, lda, cur, WG_LD, d, lane, wm, wn);
    if (more) cpa_wait();
    __syncthreads();
  }
}

// ---- prologue A: pack fp32 weights -> fp16 SMEM-image chunks
__global__ void pack_w(const float* __restrict__ W, int On, int Kfull,
                       int nch, int dst_off, int chunk_rows, int row_base) {
  int idx = blockIdx.x * 256 + threadIdx.x;
  int total = nch * On * 32;
  if (idx >= total) return;
  int c = idx / (On * 32);
  int rem = idx - c * (On * 32);
  int o = rem >> 5, k = rem & 31;
  gWP[dst_off + c * chunk_rows * WG_LD + (row_base + o) * WG_LD + k] =
      __float2half_rn(W[o * Kfull + c * 32 + k]);
}

// ---- prologue B: Mt[j][i] = sum_d Wq[d][i]*Wk[d][j] -> rows 0-127 of TV chunks
__global__ void precompute_mt(const float* __restrict__ Wq,
                              const float* __restrict__ Wk) {
  __shared__ float wkj[kD];
  const int j = blockIdx.x;
  const int i = threadIdx.x;
  wkj[i] = Wk[i * kD + j];
  __syncthreads();
  float s = 0.f;
#pragma unroll 8
  for (int dd = 0; dd < kD; dd++) s += Wq[dd * kD + i] * wkj[dd];
  int c = i >> 5, k = i & 31;
  gWP[OPK_TV + c * CHEE + j * WG_LD + k] = __float2half_rn(s);
}

__global__ __launch_bounds__(kThreads, 2)
void critic_kernel(const float* __restrict__ states,
                   const float* __restrict__ actions,
                   const float* __restrict__ b_embed,
                   const float* __restrict__ b_embed_q,
                   float* __restrict__ outV,
                   float* __restrict__ outW) {
  extern __shared__ __half smem[];
  const int b = blockIdx.x;
  const int tid = threadIdx.x;
  const int lane = tid & 31;
  const int warp = tid >> 5;
  const int wm = warp >> 3, wn = warp & 7;  // 16-warp grid

  __half* W0 = smem + OFF_W0;
  __half* W1 = smem + OFF_W1;
  float*  SCf = reinterpret_cast<float*>(smem + OFF_W0);
  __half* SCH = smem + OFF_W1;
  __half* SA = smem + OFF_SA;
  __half* T  = smem + OFF_T;
  __half* VT = smem + OFF_VT;
  __half* H  = smem + OFF_H;
  __half* E  = smem + OFF_E;
  __half* EQ = smem + OFF_EQ;

  // ---- load sa as fp16
  {
    const float* st = states + (size_t)b * kN * kOBS;
    const float* ac = actions + (size_t)b * kN * kACT;
#pragma unroll 4
    for (int j = 0; j < 32; j++) {
      int i = tid + j * kThreads;
      int t = i >> 8, c = i & 255;
      float v = (c < kOBS) ? st[t * kOBS + c] : ac[t * kACT + (c - kOBS)];
      SA[t * SA_LD + c] = __float2half_rn(v);
    }
  }

  float d4[2][4][4];
  float d2[2][2][4];
  float d1[2][1][4];

  // ======== merged e|eq: [64,256] = sa @ [We;Weq]^T ======================
  zero_acc(d4);
  staged_mm<4, 8, CHEE>(SA, SA_LD, gWP + OPK_EE, d4, W0, W1, tid, lane, wm, wn);
  if (wn < 4) {
    for_each_pair<4>(d4, lane, wm, wn, [&](int r, int c, float lo, float hi) {
      lo += __ldg(b_embed + c);
      hi += __ldg(b_embed + c + 1);
      lo = lo > 0.f ? lo : 0.01f * lo;
      hi = hi > 0.f ? hi : 0.01f * hi;
      *(__half2*)(E + r * E_LD + c) = __floats2half2_rn(lo, hi);
    });
  } else {
    for_each_pair<4>(d4, lane, wm, wn, [&](int r, int c, float lo, float hi) {
      int cl = c - 128;
      lo += __ldg(b_embed_q + cl);
      hi += __ldg(b_embed_q + cl + 1);
      lo = lo > 0.f ? lo : 0.01f * lo;
      hi = hi > 0.f ? hi : 0.01f * hi;
      *(__half2*)(EQ + r * E_LD + cl) = __floats2half2_rn(lo, hi);
    });
  }
  __syncthreads();

  // ======== merged t|v: [64,256] = e @ [Mt;Wv]^T =========================
  zero_acc(d4);
  staged_mm<4, 4, CHEE>(E, E_LD, gWP + OPK_TV, d4, W0, W1, tid, lane, wm, wn);
  if (wn < 4) {
    for_each_pair<4>(d4, lane, wm, wn, [&](int r, int c, float lo, float hi) {
      *(__half2*)(T + r * E_LD + c) = __floats2half2_rn(lo, hi);
    });
  } else {
    for_each_pair<4>(d4, lane, wm, wn, [&](int r, int c, float lo, float hi) {
      int cl = c - 128;
      VT[cl * S_LD + r] = __float2half_rn(lo);
      VT[(cl + 1) * S_LD + r] = __float2half_rn(hi);
    });
  }
  __syncthreads();

  // ======== scores = t @ e^T / sqrt(D) -> SCf fp32 (in W0) ===============
  zero_acc(d1);
  mma_block<1, 128>(T, E_LD, E, E_LD, d1, lane, wm, wn);
  for_each_pair<1>(d1, lane, wm, wn, [&](int r, int c, float lo, float hi) {
    *(float2*)(SCf + r * S_LD + c) =
        make_float2(lo * 0.08838834764831845f, hi * 0.08838834764831845f);
  });
  __syncthreads();

  // ======== row softmax: gmem fp32 + fp16 copy into SCH (W1) =============
  {
    const int r = tid >> 3;
    const int c0 = (tid & 7) * 8;
    const float* wrow = SCf + r * S_LD + c0;
    float s[8];
#pragma unroll
    for (int j = 0; j < 8; j++) s[j] = wrow[j];
    float mx = -3.0e38f;
#pragma unroll
    for (int j = 0; j < 8; j++) mx = fmaxf(mx, s[j]);
    mx = fmaxf(mx, __shfl_xor_sync(0xffffffffu, mx, 1));
    mx = fmaxf(mx, __shfl_xor_sync(0xffffffffu, mx, 2));
    mx = fmaxf(mx, __shfl_xor_sync(0xffffffffu, mx, 4));
    float sum = 0.f;
#pragma unroll
    for (int j = 0; j < 8; j++) {
      s[j] = __expf(s[j] - mx);
      sum += s[j];
    }
    sum += __shfl_xor_sync(0xffffffffu, sum, 1);
    sum += __shfl_xor_sync(0xffffffffu, sum, 2);
    sum += __shfl_xor_sync(0xffffffffu, sum, 4);
    float inv = 1.f / sum;
    float* og = outW + ((size_t)b * kN + r) * kN + c0;
#pragma unroll
    for (int j = 0; j < 8; j++) {
      float wv = s[j] * inv;
      og[j] = wv;
      SCH[r * S_LD + c0 + j] = __float2half_rn(wv);
    }
  }
  __syncthreads();

  // ======== x = weight @ v -> E ==========================================
  zero_acc(d2);
  mma_block<2, 64>(SCH, S_LD, VT, S_LD, d2, lane, wm, wn);
  for_each_pair<2>(d2, lane, wm, wn, [&](int r, int c, float lo, float hi) {
    *(__half2*)(E + r * E_LD + c) = __floats2half2_rn(lo, hi);
  });
  __syncthreads();

  // ======== h = lrelu([eq, x] @ W_f1^T) ==================================
  zero_acc(d1);
  staged_mm<1, 4, CHS>(EQ, E_LD, gWP + OPK_F1, d1, W0, W0 + 5120, tid, lane,
                       wm, wn);
  staged_mm<1, 4, CHS>(E, E_LD, gWP + OPK_F1 + 4 * CHS, d1, W0, W0 + 5120,
                       tid, lane, wm, wn);
  for_each_pair<1>(d1, lane, wm, wn, [&](int r, int c, float lo, float hi) {
    lo = lo > 0.f ? lo : 0.01f * lo;
    hi = hi > 0.f ? hi : 0.01f * hi;
    *(__half2*)(H + r * S_LD + c) = __floats2half2_rn(lo, hi);
  });

  // ======== Value = h @ W_f2^T -> gmem ===================================
  zero_acc(d1);
  staged_mm<1, 2, CHS>(H, S_LD, gWP + OPK_F2, d1, W0, W0 + 5120, tid, lane,
                       wm, wn);
  for_each_pair<1>(d1, lane, wm, wn, [&](int r, int c, float lo, float hi) {
    *(float2*)(outV + ((size_t)b * kN + r) * kFO + c) = make_float2(lo, hi);
  });
}

}  // namespace

extern "C" void kernel_launch(void* const* d_in, const int* in_sizes, int n_in,
                              void* d_out, int out_size) {
  (void)in_sizes; (void)n_in; (void)out_size;
  const float* states    = (const float*)d_in[0];
  const float* actions   = (const float*)d_in[1];
  const float* W_embed   = (const float*)d_in[2];
  const float* b_embed   = (const float*)d_in[3];
  const float* W_k       = (const float*)d_in[4];
  const float* W_q       = (const float*)d_in[5];
  const float* W_v       = (const float*)d_in[6];
  const float* W_embed_q = (const float*)d_in[7];
  const float* b_embed_q = (const float*)d_in[8];
  const float* W_f1      = (const float*)d_in[9];
  const float* W_f2      = (const float*)d_in[10];

  float* outV = (float*)d_out;                 // Value [B,N,64]
  float* outW = outV + (size_t)kB * kN * kFO;  // weight [B,N,N]

  precompute_mt<<<kD, kD>>>(W_q, W_k);
  pack_w<<<(8 * 128 * 32 + 255) / 256, 256>>>(W_embed, 128, kIN, 8, OPK_EE,
                                              256, 0);
  pack_w<<<(8 * 128 * 32 + 255) / 256, 256>>>(W_embed_q, 128, kIN, 8, OPK_EE,
                                              256, 128);
  pack_w<<<(4 * 128 * 32 + 255) / 256, 256>>>(W_v, 128, kD, 4, OPK_TV,
                                              256, 128);
  pack_w<<<(8 * 64 * 32 + 255) / 256, 256>>>(W_f1, 64, 2 * kD, 8, OPK_F1,
                                             64, 0);
  pack_w<<<(2 * 64 * 32 + 255) / 256, 256>>>(W_f2, 64, kN, 2, OPK_F2,
                                             64, 0);

  cudaFuncSetAttribute(critic_kernel,
                       cudaFuncAttributeMaxDynamicSharedMemorySize, SMEM_BYTES);
  critic_kernel<<<kB, kThreads, SMEM_BYTES>>>(states, actions, b_embed,
                                              b_embed_q, outV, outW);
}